// round 9
// baseline (speedup 1.0000x reference)
#include <cuda_runtime.h>
#include <cstdint>

#define BB 256
#define SS 2048
#define FF 64
#define KD 320   // ORDER * FF

// per-(b,f) mean of observed entries — scratch (no allocation allowed)
__device__ __align__(256) float g_mean[BB * FF];

// ---------------------------------------------------------------------------
// Pre-pass: mean[b,f] = sum_s x*mask / (sum_s mask + 1e-8)
// ---------------------------------------------------------------------------
__global__ __launch_bounds__(256) void mean_kernel(const float* __restrict__ x,
                                                   const int* __restrict__ mask) {
    int b = blockIdx.x;
    int f = threadIdx.x & 63;
    int c = threadIdx.x >> 6;          // 4 chunks of 512 steps
    const float* xb = x    + (size_t)b * SS * FF;
    const int*   mb = mask + (size_t)b * SS * FF;

    float sum = 0.f;
    int   cnt = 0;
    int s0 = c * (SS / 4), s1 = s0 + (SS / 4);
    for (int s = s0; s < s1; s++) {
        int idx = s * FF + f;
        int m = mb[idx];
        float xv = xb[idx];
        if (m) { sum += xv; cnt++; }
    }

    __shared__ float ssum[4][64];
    __shared__ int   scnt[4][64];
    ssum[c][f] = sum;
    scnt[c][f] = cnt;
    __syncthreads();
    if (threadIdx.x < 64) {
        float s4 = ssum[0][f] + ssum[1][f] + ssum[2][f] + ssum[3][f];
        int   c4 = scnt[0][f] + scnt[1][f] + scnt[2][f] + scnt[3][f];
        g_mean[b * FF + f] = s4 / ((float)c4 + 1e-8f);
    }
}

// ---------------------------------------------------------------------------
// f32x2 helpers
// ---------------------------------------------------------------------------
__device__ __forceinline__ uint64_t pack2(float a, float b) {
    uint64_t r; asm("mov.b64 %0,{%1,%2};" : "=l"(r) : "f"(a), "f"(b)); return r;
}
__device__ __forceinline__ void fma2(uint64_t& acc, uint64_t a, uint64_t b) {
    asm("fma.rn.f32x2 %0, %1, %2, %0;" : "+l"(acc) : "l"(a), "l"(b));
}
__device__ __forceinline__ uint64_t add2(uint64_t a, uint64_t b) {
    uint64_t r; asm("add.rn.f32x2 %0, %1, %2;" : "=l"(r) : "l"(a), "l"(b));
    return r;
}
__device__ __forceinline__ float hadd2(uint64_t v) {
    float lo, hi; asm("mov.b64 {%0,%1}, %2;" : "=f"(lo), "=f"(hi) : "l"(v));
    return lo + hi;
}

// ---------------------------------------------------------------------------
// Main recurrence. Grid = 128 CTAs x 256 threads, 1 CTA/SM, single wave.
// Each CTA advances TWO batches; EACH THREAD carries both batches as two
// independent instruction streams sharing one register-resident W slice —
// every stall in batch A's chain is covered by batch B's FMAs (static,
// in-warp ILP; no reliance on the cross-CTA arbiter).
//
// Thread = (fg, q): fg in [0,32) = pair of contiguous output features
// (f0 = 2*fg), q in [0,8) = K-octant (8 floats/frame). W = 80 floats/thread.
// Window register-cached per batch (5 circular 8-float slices); only the
// newest frame is re-read from smem each step.
//
// PIPELINE: at phase P the refreshed slot sN=(P+4)%5 carries W-row 4; the
// 64 FFMA2 over surviving slots (both batches) are computed pre-barrier and
// interleaved between the reduction's shfl levels.
//
// OWNERSHIP REDUCTION (per batch, 3 SHFL): L1 (xor 1) splits the 2 feature
// sums by lane parity, L2/L3 (xor 2/4) accumulate; every lane ends with the
// full sum of feature f0 + (q&1). Lanes q<2 are the writers.
// ---------------------------------------------------------------------------
__global__ __launch_bounds__(256, 1) void var_kernel(
    const float* __restrict__ x, const int* __restrict__ mask,
    const float* __restrict__ W, const float* __restrict__ bias,
    float* __restrict__ out)
{
    int tid = threadIdx.x;
    int fg  = tid >> 3;     // 0..31 feature pair
    int q   = tid & 7;      // 0..7  K-octant
    int f0  = fg << 1;
    int ko  = q << 3;
    int fv  = f0 + (q & 1); // owned feature after reduction

    __shared__ __align__(16) float win[2][5][FF];   // per-batch circular frames

    // W registers: w[g][frame-row j][pair], g in {0,1}
    uint64_t w[2][5][4];
    #pragma unroll
    for (int g = 0; g < 2; g++) {
        #pragma unroll
        for (int j = 0; j < 5; j++) {
            const float4* p4 = (const float4*)(W + (size_t)(f0 + g) * KD + j * FF + ko);
            float4 a = p4[0], c = p4[1];
            w[g][j][0] = pack2(a.x, a.y); w[g][j][1] = pack2(a.z, a.w);
            w[g][j][2] = pack2(c.x, c.y); w[g][j][3] = pack2(c.z, c.w);
        }
    }
    float bs = bias[fv];

    int b0 = blockIdx.x * 2;    // batches b0, b0+1

    // smem window init: per-feature means (both batches)
    for (int i = tid; i < 2 * 5 * FF; i += 256) {
        int h = i / (5 * FF);
        (&win[h][0][0])[i - h * 5 * FF] = g_mean[(b0 + h) * FF + (i & 63)];
    }

    // register window caches: all 5 slots = mean slice
    uint64_t wr[2][5][4];
    #pragma unroll
    for (int h = 0; h < 2; h++) {
        const float4* mp = (const float4*)(g_mean + (b0 + h) * FF + ko);
        float4 a = mp[0], c = mp[1];
        #pragma unroll
        for (int j = 0; j < 5; j++) {
            wr[h][j][0] = pack2(a.x, a.y); wr[h][j][1] = pack2(a.z, a.w);
            wr[h][j][2] = pack2(c.x, c.y); wr[h][j][3] = pack2(c.z, c.w);
        }
    }

    // scalar streams for the owned feature (used by lanes q<2 only)
    const float* xs0 = x    + (size_t)b0 * SS * FF + fv;
    const int*   ms0 = mask + (size_t)b0 * SS * FF + fv;
    float*       os0 = out  + (size_t)b0 * SS * FF + fv;
    const float* xs1 = xs0 + (size_t)SS * FF;
    const int*   ms1 = ms0 + (size_t)SS * FF;
    float*       os1 = os0 + (size_t)SS * FF;

    // Prefetch step 0 (writers only)
    float xv0 = 0.f, xv1 = 0.f; int mv0 = 0, mv1 = 0;
    if (q < 2) { xv0 = xs0[0]; mv0 = ms0[0]; xv1 = xs1[0]; mv1 = ms1[0]; }

    // Bootstrap partials for phase 0: slots s=0..3 carry rows 0..3.
    uint64_t part00 = 0, part01 = 0, part10 = 0, part11 = 0;
    #pragma unroll
    for (int s = 0; s < 4; s++) {
        #pragma unroll
        for (int o = 0; o < 4; o++) {
            fma2(part00, w[0][s][o], wr[0][s][o]);
            fma2(part01, w[1][s][o], wr[0][s][o]);
            fma2(part10, w[0][s][o], wr[1][s][o]);
            fma2(part11, w[1][s][o], wr[1][s][o]);
        }
    }

    __syncthreads();

    int t = 0;

    // Partial-FMA chunk over surviving slot s (both batches, both feats).
    #define PCHUNK(P, s)                                                       \
        if ((s) != (P)) {                                                      \
            const int jp = ((s) - (P) - 1 + 5) % 5;                            \
            _Pragma("unroll")                                                  \
            for (int o = 0; o < 4; o++) {                                      \
                fma2(np00, w[0][jp][o], wr[0][s][o]);                          \
                fma2(np01, w[1][jp][o], wr[0][s][o]);                          \
                fma2(np10, w[0][jp][o], wr[1][s][o]);                          \
                fma2(np11, w[1][jp][o], wr[1][s][o]);                          \
            }                                                                  \
        }

    // One recurrence step (both batches) at static phase P. Advances t by 1.
    #define STEP(P)                                                            \
    do {                                                                       \
        const int sN = (P + 4) % 5;                                            \
        /* critical path: refresh newest slot for both batches */              \
        {                                                                      \
            const float4* nf0 = (const float4*)(&win[0][sN][ko]);              \
            const float4* nf1 = (const float4*)(&win[1][sN][ko]);              \
            float4 a0 = nf0[0], c0 = nf0[1];                                   \
            float4 a1 = nf1[0], c1 = nf1[1];                                   \
            wr[0][sN][0] = pack2(a0.x, a0.y); wr[0][sN][1] = pack2(a0.z, a0.w);\
            wr[0][sN][2] = pack2(c0.x, c0.y); wr[0][sN][3] = pack2(c0.z, c0.w);\
            wr[1][sN][0] = pack2(a1.x, a1.y); wr[1][sN][1] = pack2(a1.z, a1.w);\
            wr[1][sN][2] = pack2(c1.x, c1.y); wr[1][sN][3] = pack2(c1.z, c1.w);\
        }                                                                      \
        /* early prefetch of next x/mask (writers only, independent) */        \
        float xn0 = 0.f, xn1 = 0.f; int mn0 = 0, mn1 = 0;                      \
        if (q < 2 && t + 1 < SS) {                                             \
            xn0 = xs0[(size_t)(t + 1) * FF]; mn0 = ms0[(size_t)(t + 1) * FF];  \
            xn1 = xs1[(size_t)(t + 1) * FF]; mn1 = ms1[(size_t)(t + 1) * FF];  \
        }                                                                      \
        /* row-4 FMAs: 2-deep chains per feature per batch */                  \
        uint64_t a00 = part00, b00 = 0, a01 = part01, b01 = 0;                 \
        uint64_t a10 = part10, b10 = 0, a11 = part11, b11 = 0;                 \
        fma2(a00, w[0][4][0], wr[0][sN][0]); fma2(b00, w[0][4][1], wr[0][sN][1]);\
        fma2(a00, w[0][4][2], wr[0][sN][2]); fma2(b00, w[0][4][3], wr[0][sN][3]);\
        fma2(a01, w[1][4][0], wr[0][sN][0]); fma2(b01, w[1][4][1], wr[0][sN][1]);\
        fma2(a01, w[1][4][2], wr[0][sN][2]); fma2(b01, w[1][4][3], wr[0][sN][3]);\
        fma2(a10, w[0][4][0], wr[1][sN][0]); fma2(b10, w[0][4][1], wr[1][sN][1]);\
        fma2(a10, w[0][4][2], wr[1][sN][2]); fma2(b10, w[0][4][3], wr[1][sN][3]);\
        fma2(a11, w[1][4][0], wr[1][sN][0]); fma2(b11, w[1][4][1], wr[1][sN][1]);\
        fma2(a11, w[1][4][2], wr[1][sN][2]); fma2(b11, w[1][4][3], wr[1][sN][3]);\
        float r00 = hadd2(add2(a00, b00));  /* batch0, feature f0   */         \
        float r01 = hadd2(add2(a01, b01));  /* batch0, feature f0+1 */         \
        float r10 = hadd2(add2(a10, b10));                                     \
        float r11 = hadd2(add2(a11, b11));                                     \
        /* ownership reduction (3 SHFL/batch), partials interleaved */         \
        uint64_t np00 = 0, np01 = 0, np10 = 0, np11 = 0;                       \
        int p = q & 1;                                                         \
        float kp0  = p ? r01 : r00;                                            \
        float snd0 = p ? r00 : r01;                                            \
        float kp1  = p ? r11 : r10;                                            \
        float snd1 = p ? r10 : r11;                                            \
        float rc0 = __shfl_xor_sync(0xffffffffu, snd0, 1);                     \
        float rc1 = __shfl_xor_sync(0xffffffffu, snd1, 1);                     \
        PCHUNK(P, 0); PCHUNK(P, 1);                                            \
        float s0 = kp0 + rc0;                                                  \
        float s1 = kp1 + rc1;                                                  \
        float d0 = __shfl_xor_sync(0xffffffffu, s0, 2);                        \
        float d1 = __shfl_xor_sync(0xffffffffu, s1, 2);                        \
        PCHUNK(P, 2); PCHUNK(P, 3);                                            \
        s0 += d0; s1 += d1;                                                    \
        float e0 = __shfl_xor_sync(0xffffffffu, s0, 4);                        \
        float e1 = __shfl_xor_sync(0xffffffffu, s1, 4);                        \
        PCHUNK(P, 4);                                                          \
        s0 += e0; s1 += e1;                                                    \
        float nv0 = mv0 ? xv0 : (s0 + bs);                                     \
        float nv1 = mv1 ? xv1 : (s1 + bs);                                     \
        if (q < 2) {                                                           \
            win[0][(P)][fv] = nv0;        /* oldest slot <- newest */          \
            win[1][(P)][fv] = nv1;                                             \
            os0[(size_t)t * FF] = nv0;                                         \
            os1[(size_t)t * FF] = nv1;                                         \
        }                                                                      \
        xv0 = xn0; mv0 = mn0; xv1 = xn1; mv1 = mn1;                            \
        part00 = np00; part01 = np01; part10 = np10; part11 = np11;            \
        __syncthreads();                                                       \
        t++;                                                                   \
    } while (0)

    // 409 * 5 = 2045 steps
    for (int it = 0; it < 409; it++) {
        STEP(0); STEP(1); STEP(2); STEP(3); STEP(4);
    }
    // epilogue: t = 2045, 2046, 2047 (phases 0,1,2 since 2045 % 5 == 0)
    STEP(0); STEP(1); STEP(2);

    #undef STEP
    #undef PCHUNK
}

// ---------------------------------------------------------------------------
extern "C" void kernel_launch(void* const* d_in, const int* in_sizes, int n_in,
                              void* d_out, int out_size) {
    const float* x    = (const float*)d_in[0];
    const int*   mask = (const int*)  d_in[1];
    const float* W    = (const float*)d_in[2];
    const float* bias = (const float*)d_in[3];
    float*       out  = (float*)d_out;

    mean_kernel<<<BB, 256>>>(x, mask);
    var_kernel<<<BB / 2, 256>>>(x, mask, W, bias, out);
}

// round 11
// speedup vs baseline: 1.3214x; 1.3214x over previous
#include <cuda_runtime.h>
#include <cstdint>

#define BB 256
#define SS 2048
#define FF 64
#define KD 320   // ORDER * FF

// per-(b,f) mean of observed entries — scratch (no allocation allowed)
__device__ __align__(256) float g_mean[BB * FF];

// ---------------------------------------------------------------------------
// Pre-pass: mean[b,f] = sum_s x*mask / (sum_s mask + 1e-8)
// Vectorized: thread = (quad, chunk); float4/int4 loads, smem tree.
// ---------------------------------------------------------------------------
__global__ __launch_bounds__(256) void mean_kernel(const float* __restrict__ x,
                                                   const int* __restrict__ mask) {
    int b    = blockIdx.x;
    int quad = threadIdx.x & 15;    // feature quad: features 4*quad..4*quad+3
    int c    = threadIdx.x >> 4;    // 16 chunks of 128 steps

    const float4* xb = (const float4*)(x    + (size_t)b * SS * FF);
    const int4*   mb = (const int4*)  (mask + (size_t)b * SS * FF);

    float4 sum = {0.f, 0.f, 0.f, 0.f};
    float4 cnt = {0.f, 0.f, 0.f, 0.f};
    int base = c * 128;
    #pragma unroll 4
    for (int s = 0; s < 128; s++) {
        int idx = (base + s) * 16 + quad;
        float4 xv = xb[idx];
        int4   m  = mb[idx];
        if (m.x) { sum.x += xv.x; cnt.x += 1.f; }
        if (m.y) { sum.y += xv.y; cnt.y += 1.f; }
        if (m.z) { sum.z += xv.z; cnt.z += 1.f; }
        if (m.w) { sum.w += xv.w; cnt.w += 1.f; }
    }

    __shared__ float ssum[16][64];
    __shared__ float scnt[16][64];
    ssum[c][quad * 4 + 0] = sum.x; ssum[c][quad * 4 + 1] = sum.y;
    ssum[c][quad * 4 + 2] = sum.z; ssum[c][quad * 4 + 3] = sum.w;
    scnt[c][quad * 4 + 0] = cnt.x; scnt[c][quad * 4 + 1] = cnt.y;
    scnt[c][quad * 4 + 2] = cnt.z; scnt[c][quad * 4 + 3] = cnt.w;
    __syncthreads();
    if (threadIdx.x < 64) {
        int f = threadIdx.x;
        float s = 0.f, n = 0.f;
        #pragma unroll
        for (int k = 0; k < 16; k++) { s += ssum[k][f]; n += scnt[k][f]; }
        g_mean[b * FF + f] = s / (n + 1e-8f);
    }
}

// ---------------------------------------------------------------------------
// f32x2 helpers
// ---------------------------------------------------------------------------
__device__ __forceinline__ uint64_t pack2(float a, float b) {
    uint64_t r; asm("mov.b64 %0,{%1,%2};" : "=l"(r) : "f"(a), "f"(b)); return r;
}
__device__ __forceinline__ void fma2(uint64_t& acc, uint64_t a, uint64_t b) {
    asm("fma.rn.f32x2 %0, %1, %2, %0;" : "+l"(acc) : "l"(a), "l"(b));
}
__device__ __forceinline__ uint64_t add2(uint64_t a, uint64_t b) {
    uint64_t r; asm("add.rn.f32x2 %0, %1, %2;" : "=l"(r) : "l"(a), "l"(b));
    return r;
}
__device__ __forceinline__ float hadd2(uint64_t v) {
    float lo, hi; asm("mov.b64 {%0,%1}, %2;" : "=f"(lo), "=f"(hi) : "l"(v));
    return lo + hi;
}
__device__ __forceinline__ uint64_t shfl_xor64(uint64_t v, int d) {
    uint32_t lo = (uint32_t)v, hi = (uint32_t)(v >> 32);
    lo = __shfl_xor_sync(0xffffffffu, lo, d);
    hi = __shfl_xor_sync(0xffffffffu, hi, d);
    return ((uint64_t)hi << 32) | lo;
}

// ---------------------------------------------------------------------------
// Main recurrence. One CTA (128 threads) per batch, 256 CTAs, 2 CTAs/SM.
// Thread = (fg, q): fg = group of 4 contiguous output features, q = K-octant.
// W register-resident (80 f32x2/thread); window register-cached as 5 circular
// 8-float frame slices; only the newest frame is re-read from smem each step.
//
// SOFTWARE PIPELINE: at phase P the refreshed slot sN=(P+4)%5 carries W-row 4;
// the 64 FFMA2 over the 4 surviving slots are computed pre-barrier ("partial").
//
// MULTI-VALUE REDUCTION (4 SHFL.32/step): each butterfly level splits
// ownership of the 4 feature sums; lane q ends with the full sum of feature
// v(q) = 2*(q&1) + ((q>>1)&1). Lanes q<4 are the writers.
//
// DOUBLE-DEPTH PREFETCH: x/mask loaded 2 steps ahead so DRAM latency
// (~300-600 cyc) is fully covered by ~2 step periods.
// ---------------------------------------------------------------------------
__global__ __launch_bounds__(128, 2) void var_kernel(
    const float* __restrict__ x, const int* __restrict__ mask,
    const float* __restrict__ W, const float* __restrict__ bias,
    float* __restrict__ out)
{
    int tid = threadIdx.x;
    int b   = blockIdx.x;
    int fg  = tid >> 3;     // 0..15 feature group
    int q   = tid & 7;      // 0..7  K-octant
    int f0  = fg << 2;
    int ko  = q << 3;
    int v   = ((q & 1) << 1) | ((q >> 1) & 1);   // owned feature after reduce
    int fv  = f0 + v;

    __shared__ __align__(16) float win[5][FF];   // circular frame buffer

    // W registers: w[g][frame-row j][pair]
    uint64_t w[4][5][4];
    #pragma unroll
    for (int g = 0; g < 4; g++) {
        #pragma unroll
        for (int j = 0; j < 5; j++) {
            const float4* p4 = (const float4*)(W + (size_t)(f0 + g) * KD + j * FF + ko);
            float4 a = p4[0], c = p4[1];
            w[g][j][0] = pack2(a.x, a.y); w[g][j][1] = pack2(a.z, a.w);
            w[g][j][2] = pack2(c.x, c.y); w[g][j][3] = pack2(c.z, c.w);
        }
    }
    float bs = bias[fv];

    // smem window init: per-feature means
    for (int i = tid; i < 5 * FF; i += 128)
        (&win[0][0])[i] = g_mean[b * FF + (i & 63)];

    // register window cache: all 5 slots = mean slice
    uint64_t wr[5][4];
    {
        const float4* mp = (const float4*)(g_mean + b * FF + ko);
        float4 a = mp[0], c = mp[1];
        #pragma unroll
        for (int j = 0; j < 5; j++) {
            wr[j][0] = pack2(a.x, a.y); wr[j][1] = pack2(a.z, a.w);
            wr[j][2] = pack2(c.x, c.y); wr[j][3] = pack2(c.z, c.w);
        }
    }

    const float* xs = x    + (size_t)b * SS * FF + fv;   // scalar owner stream
    const int*   ms = mask + (size_t)b * SS * FF + fv;
    float*       os = out  + (size_t)b * SS * FF + fv;

    // Prefetch steps 0 and 1 (owners only) — depth-2 pipeline
    float xv = 0.f, xv1 = 0.f; int mv = 0, mv1 = 0;
    if (q < 4) {
        xv  = xs[0];  mv  = ms[0];
        xv1 = xs[FF]; mv1 = ms[FF];
    }

    // Bootstrap partial for phase 0: slots s=0..3 carry rows 0..3.
    uint64_t part0 = 0, part1 = 0, part2 = 0, part3 = 0;
    #pragma unroll
    for (int s = 0; s < 4; s++) {
        #pragma unroll
        for (int o = 0; o < 4; o++) {
            fma2(part0, w[0][s][o], wr[s][o]);
            fma2(part1, w[1][s][o], wr[s][o]);
            fma2(part2, w[2][s][o], wr[s][o]);
            fma2(part3, w[3][s][o], wr[s][o]);
        }
    }

    __syncthreads();

    int t = 0;

    // Partial-FMA chunk over surviving slot s for phase P (16 FFMA2).
    #define PCHUNK(P, s)                                                       \
        if ((s) != (P)) {                                                      \
            const int jp = ((s) - (P) - 1 + 5) % 5;                            \
            _Pragma("unroll")                                                  \
            for (int o = 0; o < 4; o++) {                                      \
                fma2(np0, w[0][jp][o], wr[s][o]);                              \
                fma2(np1, w[1][jp][o], wr[s][o]);                              \
                fma2(np2, w[2][jp][o], wr[s][o]);                              \
                fma2(np3, w[3][jp][o], wr[s][o]);                              \
            }                                                                  \
        }

    // One recurrence step at static phase P. Advances t by 1.
    #define STEP(P)                                                            \
    do {                                                                       \
        /* critical path: refresh slot sN=(P+4)%5 (always W-row 4) */          \
        {                                                                      \
            const float4* nf = (const float4*)(&win[(P + 4) % 5][ko]);         \
            float4 a = nf[0], c = nf[1];                                       \
            wr[(P + 4) % 5][0] = pack2(a.x, a.y);                              \
            wr[(P + 4) % 5][1] = pack2(a.z, a.w);                              \
            wr[(P + 4) % 5][2] = pack2(c.x, c.y);                              \
            wr[(P + 4) % 5][3] = pack2(c.z, c.w);                              \
        }                                                                      \
        /* depth-2 prefetch: issue load for t+2 (owners only, independent) */  \
        float xv_n = 0.f; int mv_n = 0;                                        \
        if (q < 4 && t + 2 < SS) {                                             \
            xv_n = xs[(size_t)(t + 2) * FF];                                   \
            mv_n = ms[(size_t)(t + 2) * FF];                                   \
        }                                                                      \
        /* row-4 FMAs as two 2-deep chains + add */                            \
        uint64_t ca0 = part0, cb0 = 0, ca1 = part1, cb1 = 0;                   \
        uint64_t ca2 = part2, cb2 = 0, ca3 = part3, cb3 = 0;                   \
        {                                                                      \
            const int sN = (P + 4) % 5;                                        \
            fma2(ca0, w[0][4][0], wr[sN][0]); fma2(cb0, w[0][4][1], wr[sN][1]);\
            fma2(ca0, w[0][4][2], wr[sN][2]); fma2(cb0, w[0][4][3], wr[sN][3]);\
            fma2(ca1, w[1][4][0], wr[sN][0]); fma2(cb1, w[1][4][1], wr[sN][1]);\
            fma2(ca1, w[1][4][2], wr[sN][2]); fma2(cb1, w[1][4][3], wr[sN][3]);\
            fma2(ca2, w[2][4][0], wr[sN][0]); fma2(cb2, w[2][4][1], wr[sN][1]);\
            fma2(ca2, w[2][4][2], wr[sN][2]); fma2(cb2, w[2][4][3], wr[sN][3]);\
            fma2(ca3, w[3][4][0], wr[sN][0]); fma2(cb3, w[3][4][1], wr[sN][1]);\
            fma2(ca3, w[3][4][2], wr[sN][2]); fma2(cb3, w[3][4][3], wr[sN][3]);\
        }                                                                      \
        float r0 = hadd2(add2(ca0, cb0)), r1 = hadd2(add2(ca1, cb1));          \
        float r2 = hadd2(add2(ca2, cb2)), r3 = hadd2(add2(ca3, cb3));          \
        /* multi-value reduction, partials interleaved to cover SHFL lat. */   \
        uint64_t np0 = 0, np1 = 0, np2 = 0, np3 = 0;                           \
        /* L1 (xor 1): keep {r0,r1} if q even, {r2,r3} if q odd */             \
        uint64_t snd1 = (q & 1) ? pack2(r0, r1) : pack2(r2, r3);               \
        uint64_t kp1  = (q & 1) ? pack2(r2, r3) : pack2(r0, r1);               \
        uint64_t rc1  = shfl_xor64(snd1, 1);                                   \
        PCHUNK(P, 0); PCHUNK(P, 1);                                            \
        uint64_t v2 = add2(kp1, rc1);                                          \
        float va, vb;                                                          \
        asm("mov.b64 {%0,%1}, %2;" : "=f"(va), "=f"(vb) : "l"(v2));            \
        /* L2 (xor 2): keep first if (q&2)==0 else second */                   \
        float kp2  = (q & 2) ? vb : va;                                        \
        float snd2 = (q & 2) ? va : vb;                                        \
        float rc2  = __shfl_xor_sync(0xffffffffu, snd2, 2);                    \
        PCHUNK(P, 2); PCHUNK(P, 3);                                            \
        float r4 = kp2 + rc2;                                                  \
        /* L3 (xor 4): full sum of feature v */                                \
        float rc3 = __shfl_xor_sync(0xffffffffu, r4, 4);                       \
        PCHUNK(P, 4);                                                          \
        float rsum = r4 + rc3;                                                 \
        float nv = mv ? xv : (rsum + bs);                                      \
        if (q < 4) {                                                           \
            win[(P)][fv] = nv;            /* oldest slot <- newest */          \
            os[(size_t)t * FF] = nv;                                           \
        }                                                                      \
        xv = xv1; mv = mv1; xv1 = xv_n; mv1 = mv_n;                            \
        part0 = np0; part1 = np1; part2 = np2; part3 = np3;                    \
        __syncthreads();                                                       \
        t++;                                                                   \
    } while (0)

    // 409 * 5 = 2045 steps
    for (int it = 0; it < 409; it++) {
        STEP(0); STEP(1); STEP(2); STEP(3); STEP(4);
    }
    // epilogue: t = 2045, 2046, 2047 (phases 0,1,2 since 2045 % 5 == 0)
    STEP(0); STEP(1); STEP(2);

    #undef STEP
    #undef PCHUNK
}

// ---------------------------------------------------------------------------
extern "C" void kernel_launch(void* const* d_in, const int* in_sizes, int n_in,
                              void* d_out, int out_size) {
    const float* x    = (const float*)d_in[0];
    const int*   mask = (const int*)  d_in[1];
    const float* W    = (const float*)d_in[2];
    const float* bias = (const float*)d_in[3];
    float*       out  = (float*)d_out;

    mean_kernel<<<BB, 256>>>(x, mask);
    var_kernel<<<BB, 128>>>(x, mask, W, bias, out);
}